// round 16
// baseline (speedup 1.0000x reference)
#include <cuda_runtime.h>
#include <cuda_fp16.h>
#include <cuda_bf16.h>
#include <math.h>

#define NMAX 100000
#define EMAX 1600000
#define HID 64
#define HEADS 4
#define GDIM 256
#define OUTD 3

typedef unsigned long long ull;

// ---------------- scratch ----------------
__device__ int   d_cnt[NMAX];
__device__ int   d_rowptr[NMAX + 1];
__device__ int   d_cursor[NMAX];
__device__ int   d_csr[EMAX];
__device__ float d_dinv[NMAX];
__device__ int   d_blocksum[512];
__device__ int   d_blockoff[512];
__device__ __half d_t16[(size_t)NMAX * HID];
__device__ __half d_h16[(size_t)NMAX * HID];
__device__ __half d_hgh[(size_t)NMAX * GDIM];
__device__ __half d_hatt[(size_t)NMAX * GDIM];
__device__ float d_att [(size_t)NMAX * 8];
__device__ float d_wz  [64 * 8];
__device__ __half d_w216[64 * 64];
__device__ __half d_w316[64 * 64];
__device__ __half d_wg16[64 * 256];
__device__ __half d_wc116[256 * 64];

// ---------------- helpers ----------------
__device__ __forceinline__ ull pk2(float lo, float hi) {
    ull r; asm("mov.b64 %0,{%1,%2};" : "=l"(r) : "f"(lo), "f"(hi)); return r;
}
__device__ __forceinline__ float2 up2(ull v) {
    float2 r; asm("mov.b64 {%0,%1},%2;" : "=f"(r.x), "=f"(r.y) : "l"(v)); return r;
}
__device__ __forceinline__ void ffma2(ull& d, ull a, ull b) {
    asm("fma.rn.f32x2 %0,%1,%2,%0;" : "+l"(d) : "l"(a), "l"(b));
}
__device__ __forceinline__ void mma16816(float* c, unsigned a0, unsigned a1,
                                         unsigned a2, unsigned a3,
                                         unsigned b0, unsigned b1) {
    asm volatile(
        "mma.sync.aligned.m16n8k16.row.col.f32.f16.f16.f32 "
        "{%0,%1,%2,%3},{%4,%5,%6,%7},{%8,%9},{%0,%1,%2,%3};"
        : "+f"(c[0]), "+f"(c[1]), "+f"(c[2]), "+f"(c[3])
        : "r"(a0), "r"(a1), "r"(a2), "r"(a3), "r"(b0), "r"(b1));
}

// ---------------- preprocessing ----------------
__global__ void k_count(const int* __restrict__ dst, int e) {
    int i = blockIdx.x * blockDim.x + threadIdx.x;
    if (i < e) atomicAdd(&d_cnt[dst[i]], 1);
}

__global__ void k_scan_blocks(int n) {
    __shared__ int sh[1024];
    int i = blockIdx.x * 1024 + threadIdx.x;
    int v = (i < n) ? d_cnt[i] : 0;
    sh[threadIdx.x] = v;
    __syncthreads();
    for (int off = 1; off < 1024; off <<= 1) {
        int t = (threadIdx.x >= off) ? sh[threadIdx.x - off] : 0;
        __syncthreads();
        if (threadIdx.x >= off) sh[threadIdx.x] += t;
        __syncthreads();
    }
    if (i < n) d_rowptr[i] = sh[threadIdx.x] - v;
    if (threadIdx.x == 1023) d_blocksum[blockIdx.x] = sh[1023];
}

__global__ void k_scan_off(int nb) {
    __shared__ int sh[512];
    int t = threadIdx.x;
    int v = (t < nb) ? d_blocksum[t] : 0;
    sh[t] = v;
    __syncthreads();
    for (int off = 1; off < 512; off <<= 1) {
        int u = (t >= off) ? sh[t - off] : 0;
        __syncthreads();
        if (t >= off) sh[t] += u;
        __syncthreads();
    }
    if (t < nb) d_blockoff[t] = sh[t] - v;
}

__global__ void k_fixup(int n, int e) {
    int i = blockIdx.x * blockDim.x + threadIdx.x;
    if (i < n) {
        int rp = d_rowptr[i] + d_blockoff[i >> 10];
        d_rowptr[i] = rp;
        d_cursor[i] = rp;
        d_dinv[i] = rsqrtf((float)(d_cnt[i] + 1));
        if (i == 0) d_rowptr[n] = e;
    }
}

__global__ void k_fill(const int* __restrict__ src, const int* __restrict__ dst, int e) {
    int i = blockIdx.x * blockDim.x + threadIdx.x;
    if (i < e) {
        int d = dst[i];
        int p = atomicAdd(&d_cursor[d], 1);
        d_csr[p] = src[i];
    }
}

// weight fp16 conversion + wz fold (block 160)
__global__ void k_prep(const float* __restrict__ w2, const float* __restrict__ w3,
                       const float* __restrict__ wg, const float* __restrict__ wc1,
                       const float* __restrict__ att_src, const float* __restrict__ att_dst) {
    if (blockIdx.x == 160) {
        int tid = threadIdx.x;
        int k = tid >> 2, h = tid & 3;
        float ss = 0.f, sd = 0.f;
#pragma unroll
        for (int c = 0; c < 64; c++) {
            float w = wg[k * 256 + h * 64 + c];
            ss += w * att_src[h * 64 + c];
            sd += w * att_dst[h * 64 + c];
        }
        d_wz[k * 8 + h] = ss;
        d_wz[k * 8 + 4 + h] = sd;
        return;
    }
    int i = blockIdx.x * blockDim.x + threadIdx.x;
    if (i < 4096) d_w216[i] = __float2half_rn(w2[i]);
    else if (i < 8192) d_w316[i - 4096] = __float2half_rn(w3[i - 4096]);
    else if (i < 24576) d_wg16[i - 8192] = __float2half_rn(wg[i - 8192]);
    else if (i < 40960) d_wc116[i - 24576] = __float2half_rn(wc1[i - 24576]);
}

// ---------------- layer-1 GEMM (fp32 A, K=8) -> dinv-scaled fp16 out ----------
__global__ void k_gemm1(const float* __restrict__ A, const float* __restrict__ B,
                        __half* __restrict__ C, int n) {
    __shared__ float AsT[8][72];
    __shared__ ull   Bs2[8][32];
    int row0 = blockIdx.x * 64;
    int tid = threadIdx.x;
    int tx = tid & 15, ty = tid >> 4;
    ull acc[4][2] = {{0ull,0ull},{0ull,0ull},{0ull,0ull},{0ull,0ull}};
    for (int i = tid; i < 64 * 8; i += 256) {
        int r = i >> 3, k = i & 7;
        AsT[k][r] = (row0 + r < n) ? A[(size_t)(row0 + r) * 8 + k] : 0.f;
    }
    for (int i = tid; i < 8 * 32; i += 256) {
        int kk = i >> 5, c2 = i & 31;
        float2 bv = *reinterpret_cast<const float2*>(&B[(size_t)kk * 64 + 2 * c2]);
        Bs2[kk][c2] = pk2(bv.x, bv.y);
    }
    __syncthreads();
#pragma unroll
    for (int kk = 0; kk < 8; kk++) {
        float4 a4 = *reinterpret_cast<const float4*>(&AsT[kk][ty * 4]);
        ulonglong2 bp = *reinterpret_cast<const ulonglong2*>(&Bs2[kk][tx * 2]);
        ull b01 = bp.x, b23 = bp.y;
        ull a0 = pk2(a4.x, a4.x), a1 = pk2(a4.y, a4.y);
        ull a2 = pk2(a4.z, a4.z), a3 = pk2(a4.w, a4.w);
        ffma2(acc[0][0], a0, b01); ffma2(acc[0][1], a0, b23);
        ffma2(acc[1][0], a1, b01); ffma2(acc[1][1], a1, b23);
        ffma2(acc[2][0], a2, b01); ffma2(acc[2][1], a2, b23);
        ffma2(acc[3][0], a3, b01); ffma2(acc[3][1], a3, b23);
    }
#pragma unroll
    for (int i = 0; i < 4; i++) {
        int r = row0 + ty * 4 + i;
        if (r < n) {
            float dv = d_dinv[r];
            float2 c01 = up2(acc[i][0]), c23 = up2(acc[i][1]);
            __half2 h01 = __floats2half2_rn(dv * c01.x, dv * c01.y);
            __half2 h23 = __floats2half2_rn(dv * c23.x, dv * c23.y);
            uint2 v;
            v.x = *reinterpret_cast<unsigned*>(&h01);
            v.y = *reinterpret_cast<unsigned*>(&h23);
            *reinterpret_cast<uint2*>(&C[(size_t)r * 64 + tx * 4]) = v;
        }
    }
}

// ---------------- fp16 tensor-core GEMM (m16n8k16), tile 128x64 ---------------
__global__ void k_gemm_h(const __half* __restrict__ A, const __half* __restrict__ B16,
                         void* __restrict__ Cv, int n, int K, int ncols, int mode,
                         const float* __restrict__ bc1, const float* __restrict__ wc2,
                         const float* __restrict__ bc2, float* __restrict__ outp) {
    __shared__ __align__(16) unsigned char smbuf[34944];
    __half (*As)[72] = (__half(*)[72])smbuf;
    __half (*Bt)[72] = (__half(*)[72])(smbuf + 18432);
    float (*Z)[68]  = (float(*)[68])smbuf;

    int row0 = blockIdx.x * 128;
    int col0 = blockIdx.y * 64;
    int tid = threadIdx.x;
    int w = tid >> 5, lane = tid & 31;
    int qr = lane >> 2, q = lane & 3;

    float acc[8][4];
#pragma unroll
    for (int i = 0; i < 8; i++)
#pragma unroll
        for (int j = 0; j < 4; j++) acc[i][j] = 0.f;

    for (int k0 = 0; k0 < K; k0 += 64) {
        for (int i = tid * 8; i < 128 * 64; i += 256 * 8) {
            int r = i >> 6, k = i & 63;
            uint4 v = make_uint4(0u, 0u, 0u, 0u);
            if (row0 + r < n)
                v = *reinterpret_cast<const uint4*>(&A[(size_t)(row0 + r) * K + k0 + k]);
            *reinterpret_cast<uint4*>(&As[r][k]) = v;
        }
        for (int i = tid; i < 64 * 64; i += 256) {
            int c = i & 63, k = i >> 6;
            Bt[c][k] = B16[(size_t)(k0 + k) * ncols + col0 + c];
        }
        __syncthreads();
#pragma unroll
        for (int ks = 0; ks < 4; ks++) {
            int kb = ks * 16 + 2 * q;
            unsigned a0 = *reinterpret_cast<const unsigned*>(&As[w * 16 + qr][kb]);
            unsigned a1 = *reinterpret_cast<const unsigned*>(&As[w * 16 + qr + 8][kb]);
            unsigned a2 = *reinterpret_cast<const unsigned*>(&As[w * 16 + qr][kb + 8]);
            unsigned a3 = *reinterpret_cast<const unsigned*>(&As[w * 16 + qr + 8][kb + 8]);
#pragma unroll
            for (int nt = 0; nt < 8; nt++) {
                unsigned b0 = *reinterpret_cast<const unsigned*>(&Bt[nt * 8 + qr][kb]);
                unsigned b1 = *reinterpret_cast<const unsigned*>(&Bt[nt * 8 + qr][kb + 8]);
                mma16816(acc[nt], a0, a1, a2, a3, b0, b1);
            }
        }
        __syncthreads();
    }

    int r1 = row0 + w * 16 + qr;
    int r2 = r1 + 8;
    if (mode == 2 || mode == 3) {
        float dv1 = 1.f, dv2 = 1.f;
        if (mode == 3) {
            if (r1 < n) dv1 = d_dinv[r1];
            if (r2 < n) dv2 = d_dinv[r2];
        }
        __half* C = (__half*)Cv;
#pragma unroll
        for (int nt = 0; nt < 8; nt++) {
            int cb = col0 + nt * 8 + 2 * q;
            if (r1 < n) *reinterpret_cast<__half2*>(&C[(size_t)r1 * ncols + cb]) =
                __floats2half2_rn(dv1 * acc[nt][0], dv1 * acc[nt][1]);
            if (r2 < n) *reinterpret_cast<__half2*>(&C[(size_t)r2 * ncols + cb]) =
                __floats2half2_rn(dv2 * acc[nt][2], dv2 * acc[nt][3]);
        }
    } else {
#pragma unroll
        for (int nt = 0; nt < 8; nt++) {
            int cb = nt * 8 + 2 * q;
            Z[w * 16 + qr][cb]     = fmaxf(acc[nt][0] + bc1[cb], 0.f);
            Z[w * 16 + qr][cb + 1] = fmaxf(acc[nt][1] + bc1[cb + 1], 0.f);
            Z[w * 16 + qr + 8][cb]     = fmaxf(acc[nt][2] + bc1[cb], 0.f);
            Z[w * 16 + qr + 8][cb + 1] = fmaxf(acc[nt][3] + bc1[cb + 1], 0.f);
        }
        __syncthreads();
        if (tid < 128) {
            int node = row0 + tid;
            if (node < n) {
                float l0 = bc2[0], l1 = bc2[1], l2 = bc2[2];
#pragma unroll
                for (int k = 0; k < 64; k++) {
                    float zv = Z[tid][k];
                    l0 += zv * wc2[k * 3 + 0];
                    l1 += zv * wc2[k * 3 + 1];
                    l2 += zv * wc2[k * 3 + 2];
                }
                float mx = fmaxf(l0, fmaxf(l1, l2));
                float s = __expf(l0 - mx) + __expf(l1 - mx) + __expf(l2 - mx);
                float ls = mx + logf(s);
                outp[(size_t)node * 3 + 0] = l0 - ls;
                outp[(size_t)node * 3 + 1] = l1 - ls;
                outp[(size_t)node * 3 + 2] = l2 - ls;
            }
        }
    }
}

// ---------------- GCN aggregation (warp per node, unroll 8) -------------------
__global__ void k_gcn_agg(const __half* __restrict__ t, const __half* hin,
                          const float* __restrict__ bias, __half* hout,
                          int n, int doAtt) {
    __shared__ int   g_s[8][64];
    __shared__ float Wz[64][8];
    int tid = threadIdx.x;
    if (doAtt) {
        for (int i = tid; i < 512; i += 256) Wz[i >> 3][i & 7] = d_wz[i];
        __syncthreads();
    }
    int ws = tid >> 5;
    int w = (blockIdx.x * blockDim.x + tid) >> 5;
    int lane = tid & 31;
    if (w >= n) return;
    int i0 = d_rowptr[w], i1 = d_rowptr[w + 1];
    float2 tv = __half22float2(reinterpret_cast<const __half2*>(t + (size_t)w * 64)[lane]);
    float a0 = tv.x, a1 = tv.y;

    for (int base = i0; base < i1; base += 64) {
        int cnt = min(64, i1 - base);
        for (int j = lane; j < cnt; j += 32) g_s[ws][j] = d_csr[base + j];
        __syncwarp();
        int j = 0;
        for (; j + 7 < cnt; j += 8) {
            float2 x0 = __half22float2(reinterpret_cast<const __half2*>(t + (size_t)g_s[ws][j] * 64)[lane]);
            float2 x1 = __half22float2(reinterpret_cast<const __half2*>(t + (size_t)g_s[ws][j + 1] * 64)[lane]);
            float2 x2 = __half22float2(reinterpret_cast<const __half2*>(t + (size_t)g_s[ws][j + 2] * 64)[lane]);
            float2 x3 = __half22float2(reinterpret_cast<const __half2*>(t + (size_t)g_s[ws][j + 3] * 64)[lane]);
            float2 x4 = __half22float2(reinterpret_cast<const __half2*>(t + (size_t)g_s[ws][j + 4] * 64)[lane]);
            float2 x5 = __half22float2(reinterpret_cast<const __half2*>(t + (size_t)g_s[ws][j + 5] * 64)[lane]);
            float2 x6 = __half22float2(reinterpret_cast<const __half2*>(t + (size_t)g_s[ws][j + 6] * 64)[lane]);
            float2 x7 = __half22float2(reinterpret_cast<const __half2*>(t + (size_t)g_s[ws][j + 7] * 64)[lane]);
            a0 += (x0.x + x1.x) + (x2.x + x3.x) + (x4.x + x5.x) + (x6.x + x7.x);
            a1 += (x0.y + x1.y) + (x2.y + x3.y) + (x4.y + x5.y) + (x6.y + x7.y);
        }
        for (; j < cnt; ++j) {
            float2 xs = __half22float2(reinterpret_cast<const __half2*>(t + (size_t)g_s[ws][j] * 64)[lane]);
            a0 += xs.x; a1 += xs.y;
        }
        __syncwarp();
    }
    float dv = d_dinv[w];
    float2 bv = *reinterpret_cast<const float2*>(bias + 2 * lane);
    a0 = fmaxf(dv * a0 + bv.x, 0.f);
    a1 = fmaxf(dv * a1 + bv.y, 0.f);
    if (hin) {
        float2 hv = __half22float2(reinterpret_cast<const __half2*>(hin + (size_t)w * 64)[lane]);
        a0 += hv.x; a1 += hv.y;
    }
    reinterpret_cast<__half2*>(hout + (size_t)w * 64)[lane] = __floats2half2_rn(a0, a1);

    if (doAtt) {
        float p0 = a0 * Wz[2 * lane][0] + a1 * Wz[2 * lane + 1][0];
        float p1 = a0 * Wz[2 * lane][1] + a1 * Wz[2 * lane + 1][1];
        float p2 = a0 * Wz[2 * lane][2] + a1 * Wz[2 * lane + 1][2];
        float p3 = a0 * Wz[2 * lane][3] + a1 * Wz[2 * lane + 1][3];
        float p4 = a0 * Wz[2 * lane][4] + a1 * Wz[2 * lane + 1][4];
        float p5 = a0 * Wz[2 * lane][5] + a1 * Wz[2 * lane + 1][5];
        float p6 = a0 * Wz[2 * lane][6] + a1 * Wz[2 * lane + 1][6];
        float p7 = a0 * Wz[2 * lane][7] + a1 * Wz[2 * lane + 1][7];
#pragma unroll
        for (int off = 16; off > 0; off >>= 1) {
            p0 += __shfl_xor_sync(0xffffffffu, p0, off);
            p1 += __shfl_xor_sync(0xffffffffu, p1, off);
            p2 += __shfl_xor_sync(0xffffffffu, p2, off);
            p3 += __shfl_xor_sync(0xffffffffu, p3, off);
            p4 += __shfl_xor_sync(0xffffffffu, p4, off);
            p5 += __shfl_xor_sync(0xffffffffu, p5, off);
            p6 += __shfl_xor_sync(0xffffffffu, p6, off);
            p7 += __shfl_xor_sync(0xffffffffu, p7, off);
        }
        if (lane == 0) {
            *reinterpret_cast<float4*>(d_att + (size_t)w * 8)     = make_float4(p0, p1, p2, p3);
            *reinterpret_cast<float4*>(d_att + (size_t)w * 8 + 4) = make_float4(p4, p5, p6, p7);
        }
    }
}

// ---------------- GAT aggregation: 2 warps per node (head pairs) --------------
#define ONLINE(mh, dh, ev) { float nm = fmaxf(mh, ev); dh = dh * __expf(mh - nm) + __expf(ev - nm); mh = nm; }
#define LRELU(x) ((x) > 0.f ? (x) : 0.2f * (x))

__global__ void k_gat(const float* __restrict__ bg, __half* __restrict__ hatt, int n) {
    __shared__ int    s_csr[8][64];
    __shared__ float2 s_al[8][64];
    int tid = threadIdx.x;
    int ws = tid >> 5;
    int lane = tid & 31;
    int gw = (blockIdx.x * blockDim.x + tid) >> 5;
    int v = gw >> 1, sub = gw & 1;        // sub selects heads {2sub, 2sub+1}
    if (v >= n) return;
    const float4* av4 = reinterpret_cast<const float4*>(d_att + (size_t)v * 8);
    float4 asv = av4[0], adv = av4[1];
    float as0 = sub ? asv.z : asv.x, as1 = sub ? asv.w : asv.y;
    float ad0 = sub ? adv.z : adv.x, ad1 = sub ? adv.w : adv.y;
    int i0 = d_rowptr[v], i1 = d_rowptr[v + 1];

    // pass 1 (this warp's 2 heads) + cache first 64 edges' logits
    float m0 = -1e30f, m1 = -1e30f, s0 = 0.f, s1 = 0.f;
    for (int idx = i0 + lane; idx < i1; idx += 32) {
        int sn = d_csr[idx];
        float4 a = *reinterpret_cast<const float4*>(d_att + (size_t)sn * 8);
        float ax = sub ? a.z : a.x, ay = sub ? a.w : a.y;
        float e0 = LRELU(ax + ad0), e1 = LRELU(ay + ad1);
        int j = idx - i0;
        if (j < 64) { s_csr[ws][j] = sn; s_al[ws][j] = make_float2(e0, e1); }
        ONLINE(m0, s0, e0); ONLINE(m1, s1, e1);
    }
#pragma unroll
    for (int off = 16; off > 0; off >>= 1) {
#define RED(mh, dh) { float om = __shfl_xor_sync(0xffffffffu, mh, off); \
                      float od = __shfl_xor_sync(0xffffffffu, dh, off); \
                      float nm = fmaxf(mh, om); \
                      dh = dh * __expf(mh - nm) + od * __expf(om - nm); mh = nm; }
        RED(m0, s0) RED(m1, s1)
#undef RED
    }
    float e0 = LRELU(as0 + ad0); ONLINE(m0, s0, e0);
    float e1 = LRELU(as1 + ad1); ONLINE(m1, s1, e1);
    float inv0 = 1.f / (s0 + 1e-16f), inv1 = 1.f / (s1 + 1e-16f);

    // self contribution: this warp covers half2 cols [sub*64, sub*64+64)
    int hb = sub * 64;
    ull acc0, acc1;
    {
        float af0 = __expf(e0 - m0) * inv0, af1 = __expf(e1 - m1) * inv1;
        const __half2* hv2 = reinterpret_cast<const __half2*>(d_hgh + (size_t)v * 256);
        float2 f0 = __half22float2(hv2[hb + lane]);
        float2 f1 = __half22float2(hv2[hb + 32 + lane]);
        acc0 = pk2(af0 * f0.x, af0 * f0.y);
        acc1 = pk2(af1 * f1.x, af1 * f1.y);
    }

    // pass 2 chunks: strided alpha staging, then serial aggregation (unroll 4)
    for (int base = i0; base < i1; base += 64) {
        int cnt = min(64, i1 - base);
        if (base == i0) {
            for (int j = lane; j < cnt; j += 32) {
                float2 ev = s_al[ws][j];
                s_al[ws][j] = make_float2(__expf(ev.x - m0) * inv0,
                                          __expf(ev.y - m1) * inv1);
            }
        } else {
            for (int j = lane; j < cnt; j += 32) {
                int sn = d_csr[base + j];
                s_csr[ws][j] = sn;
                float4 a = *reinterpret_cast<const float4*>(d_att + (size_t)sn * 8);
                float ax = sub ? a.z : a.x, ay = sub ? a.w : a.y;
                s_al[ws][j] = make_float2(__expf(LRELU(ax + ad0) - m0) * inv0,
                                          __expf(LRELU(ay + ad1) - m1) * inv1);
            }
        }
        __syncwarp();
        int j = 0;
        for (; j + 3 < cnt; j += 4) {
            int sn0 = s_csr[ws][j],     sn1 = s_csr[ws][j + 1];
            int sn2 = s_csr[ws][j + 2], sn3 = s_csr[ws][j + 3];
            float2 A0 = s_al[ws][j],     A1 = s_al[ws][j + 1];
            float2 A2 = s_al[ws][j + 2], A3 = s_al[ws][j + 3];
            const __half2* p0 = reinterpret_cast<const __half2*>(d_hgh + (size_t)sn0 * 256);
            const __half2* p1 = reinterpret_cast<const __half2*>(d_hgh + (size_t)sn1 * 256);
            const __half2* p2 = reinterpret_cast<const __half2*>(d_hgh + (size_t)sn2 * 256);
            const __half2* p3 = reinterpret_cast<const __half2*>(d_hgh + (size_t)sn3 * 256);
            float2 f00 = __half22float2(p0[hb + lane]);
            float2 f01 = __half22float2(p0[hb + 32 + lane]);
            float2 f10 = __half22float2(p1[hb + lane]);
            float2 f11 = __half22float2(p1[hb + 32 + lane]);
            float2 f20 = __half22float2(p2[hb + lane]);
            float2 f21 = __half22float2(p2[hb + 32 + lane]);
            float2 f30 = __half22float2(p3[hb + lane]);
            float2 f31 = __half22float2(p3[hb + 32 + lane]);
            ffma2(acc0, pk2(A0.x, A0.x), pk2(f00.x, f00.y));
            ffma2(acc1, pk2(A0.y, A0.y), pk2(f01.x, f01.y));
            ffma2(acc0, pk2(A1.x, A1.x), pk2(f10.x, f10.y));
            ffma2(acc1, pk2(A1.y, A1.y), pk2(f11.x, f11.y));
            ffma2(acc0, pk2(A2.x, A2.x), pk2(f20.x, f20.y));
            ffma2(acc1, pk2(A2.y, A2.y), pk2(f21.x, f21.y));
            ffma2(acc0, pk2(A3.x, A3.x), pk2(f30.x, f30.y));
            ffma2(acc1, pk2(A3.y, A3.y), pk2(f31.x, f31.y));
        }
        for (; j < cnt; ++j) {
            int sn = s_csr[ws][j];
            float2 Aa = s_al[ws][j];
            const __half2* p0 = reinterpret_cast<const __half2*>(d_hgh + (size_t)sn * 256);
            float2 f0 = __half22float2(p0[hb + lane]);
            float2 f1 = __half22float2(p0[hb + 32 + lane]);
            ffma2(acc0, pk2(Aa.x, Aa.x), pk2(f0.x, f0.y));
            ffma2(acc1, pk2(Aa.y, Aa.y), pk2(f1.x, f1.y));
        }
        __syncwarp();
    }
    __half2* ov = reinterpret_cast<__half2*>(hatt + (size_t)v * 256);
    {
        float2 a = up2(acc0);
        float2 bgv = *reinterpret_cast<const float2*>(&bg[sub * 128 + 2 * lane]);
        ov[hb + lane] = __floats2half2_rn(a.x + bgv.x, a.y + bgv.y);
        float2 b = up2(acc1);
        float2 bgw = *reinterpret_cast<const float2*>(&bg[sub * 128 + 64 + 2 * lane]);
        ov[hb + 32 + lane] = __floats2half2_rn(b.x + bgw.x, b.y + bgw.y);
    }
}

// ---------------- launch ----------------
extern "C" void kernel_launch(void* const* d_in, const int* in_sizes, int n_in,
                              void* d_out, int out_size) {
    const float* x        = (const float*)d_in[0];
    const int*   ei       = (const int*)d_in[1];
    const float* w1       = (const float*)d_in[2];
    const float* b1       = (const float*)d_in[3];
    const float* w2       = (const float*)d_in[4];
    const float* b2       = (const float*)d_in[5];
    const float* w3       = (const float*)d_in[6];
    const float* b3       = (const float*)d_in[7];
    const float* wg       = (const float*)d_in[8];
    const float* bg       = (const float*)d_in[9];
    const float* att_src  = (const float*)d_in[10];
    const float* att_dst  = (const float*)d_in[11];
    const float* wc1      = (const float*)d_in[12];
    const float* bc1      = (const float*)d_in[13];
    const float* wc2      = (const float*)d_in[14];
    const float* bc2      = (const float*)d_in[15];
    float* out = (float*)d_out;

    int n = in_sizes[0] / 8;
    int e = in_sizes[1] / 2;
    const int* src = ei;
    const int* dst = ei + e;

    __half *t16, *h16, *hgh, *hatt, *w216, *w316, *wg16, *wc116;
    int* cnt;
    cudaGetSymbolAddress((void**)&t16,   d_t16);
    cudaGetSymbolAddress((void**)&h16,   d_h16);
    cudaGetSymbolAddress((void**)&hgh,   d_hgh);
    cudaGetSymbolAddress((void**)&hatt,  d_hatt);
    cudaGetSymbolAddress((void**)&w216,  d_w216);
    cudaGetSymbolAddress((void**)&w316,  d_w316);
    cudaGetSymbolAddress((void**)&wg16,  d_wg16);
    cudaGetSymbolAddress((void**)&wc116, d_wc116);
    cudaGetSymbolAddress((void**)&cnt,   d_cnt);

    int nb1024 = (n + 1023) / 1024;
    int gN = (n + 255) / 256;
    int gE = (e + 255) / 256;
    int gW = (n + 7) / 8;          // warp-per-node kernels
    int gW2 = (n + 3) / 4;         // 2-warps-per-node kernel (4 nodes/block)
    int gM64 = (n + 63) / 64;
    int gM = (n + 127) / 128;

    // CSR build + weight prep
    cudaMemsetAsync(cnt, 0, (size_t)n * sizeof(int));
    k_count<<<gE, 256>>>(dst, e);
    k_scan_blocks<<<nb1024, 1024>>>(n);
    k_scan_off<<<1, 512>>>(nb1024);
    k_fixup<<<gN, 256>>>(n, e);
    k_fill<<<gE, 256>>>(src, dst, e);
    k_prep<<<161, 256>>>(w2, w3, wg, wc1, att_src, att_dst);

    // GCN layer 1
    k_gemm1<<<gM64, 256>>>(x, w1, t16, n);
    k_gcn_agg<<<gW, 256>>>(t16, nullptr, b1, h16, n, 0);
    // GCN layer 2 (residual, in-place h16)
    k_gemm_h<<<dim3(gM, 1), 256>>>(h16, w216, t16, n, 64, 64, 3, nullptr, nullptr, nullptr, nullptr);
    k_gcn_agg<<<gW, 256>>>(t16, h16, b2, h16, n, 0);
    // GCN layer 3 (residual + fused attention logits)
    k_gemm_h<<<dim3(gM, 1), 256>>>(h16, w316, t16, n, 64, 64, 3, nullptr, nullptr, nullptr, nullptr);
    k_gcn_agg<<<gW, 256>>>(t16, h16, b3, h16, n, 1);

    // GAT
    k_gemm_h<<<dim3(gM, 4), 256>>>(h16, wg16, hgh, n, 64, 256, 2, nullptr, nullptr, nullptr, nullptr);
    k_gat<<<gW2, 256>>>(bg, hatt, n);

    // classifier MLP + log_softmax
    k_gemm_h<<<dim3(gM, 1), 256>>>(hatt, wc116, nullptr, n, 256, 64, 1, bc1, wc2, bc2, out);
}

// round 17
// speedup vs baseline: 1.1312x; 1.1312x over previous
#include <cuda_runtime.h>
#include <cuda_fp16.h>
#include <cuda_bf16.h>
#include <math.h>

#define NMAX 100000
#define EMAX 1600000
#define HID 64
#define HEADS 4
#define GDIM 256
#define OUTD 3

typedef unsigned long long ull;

// ---------------- scratch ----------------
__device__ int   d_cnt[NMAX];
__device__ int   d_rowptr[NMAX + 1];
__device__ int   d_cursor[NMAX];
__device__ int   d_csr[EMAX];
__device__ float d_dinv[NMAX];
__device__ int   d_blocksum[512];
__device__ int   d_blockoff[512];
__device__ __half d_t16[(size_t)NMAX * HID];
__device__ __half d_h16[(size_t)NMAX * HID];
__device__ __half d_hgh[(size_t)NMAX * GDIM];
__device__ __half d_hatt[(size_t)NMAX * GDIM];
__device__ float d_att [(size_t)NMAX * 8];
__device__ float d_wz  [64 * 8];
__device__ __half d_w216[64 * 64];
__device__ __half d_w316[64 * 64];
__device__ __half d_wg16[64 * 256];
__device__ __half d_wc116[256 * 64];

// ---------------- helpers ----------------
__device__ __forceinline__ ull pk2(float lo, float hi) {
    ull r; asm("mov.b64 %0,{%1,%2};" : "=l"(r) : "f"(lo), "f"(hi)); return r;
}
__device__ __forceinline__ float2 up2(ull v) {
    float2 r; asm("mov.b64 {%0,%1},%2;" : "=f"(r.x), "=f"(r.y) : "l"(v)); return r;
}
__device__ __forceinline__ void ffma2(ull& d, ull a, ull b) {
    asm("fma.rn.f32x2 %0,%1,%2,%0;" : "+l"(d) : "l"(a), "l"(b));
}
__device__ __forceinline__ void mma16816(float* c, unsigned a0, unsigned a1,
                                         unsigned a2, unsigned a3,
                                         unsigned b0, unsigned b1) {
    asm volatile(
        "mma.sync.aligned.m16n8k16.row.col.f32.f16.f16.f32 "
        "{%0,%1,%2,%3},{%4,%5,%6,%7},{%8,%9},{%0,%1,%2,%3};"
        : "+f"(c[0]), "+f"(c[1]), "+f"(c[2]), "+f"(c[3])
        : "r"(a0), "r"(a1), "r"(a2), "r"(a3), "r"(b0), "r"(b1));
}

// ---------------- preprocessing ----------------
__global__ void k_count(const int* __restrict__ dst, int e) {
    int i = blockIdx.x * blockDim.x + threadIdx.x;
    if (i < e) atomicAdd(&d_cnt[dst[i]], 1);
}

__global__ void k_scan_blocks(int n) {
    __shared__ int sh[1024];
    int i = blockIdx.x * 1024 + threadIdx.x;
    int v = (i < n) ? d_cnt[i] : 0;
    sh[threadIdx.x] = v;
    __syncthreads();
    for (int off = 1; off < 1024; off <<= 1) {
        int t = (threadIdx.x >= off) ? sh[threadIdx.x - off] : 0;
        __syncthreads();
        if (threadIdx.x >= off) sh[threadIdx.x] += t;
        __syncthreads();
    }
    if (i < n) d_rowptr[i] = sh[threadIdx.x] - v;
    if (threadIdx.x == 1023) d_blocksum[blockIdx.x] = sh[1023];
}

__global__ void k_scan_off(int nb) {
    __shared__ int sh[512];
    int t = threadIdx.x;
    int v = (t < nb) ? d_blocksum[t] : 0;
    sh[t] = v;
    __syncthreads();
    for (int off = 1; off < 512; off <<= 1) {
        int u = (t >= off) ? sh[t - off] : 0;
        __syncthreads();
        if (t >= off) sh[t] += u;
        __syncthreads();
    }
    if (t < nb) d_blockoff[t] = sh[t] - v;
}

__global__ void k_fixup(int n, int e) {
    int i = blockIdx.x * blockDim.x + threadIdx.x;
    if (i < n) {
        int rp = d_rowptr[i] + d_blockoff[i >> 10];
        d_rowptr[i] = rp;
        d_cursor[i] = rp;
        d_dinv[i] = rsqrtf((float)(d_cnt[i] + 1));
        if (i == 0) d_rowptr[n] = e;
    }
}

__global__ void k_fill(const int* __restrict__ src, const int* __restrict__ dst, int e) {
    int i = blockIdx.x * blockDim.x + threadIdx.x;
    if (i < e) {
        int d = dst[i];
        int p = atomicAdd(&d_cursor[d], 1);
        d_csr[p] = src[i];
    }
}

// weight fp16 conversion + wz fold (block 160)
__global__ void k_prep(const float* __restrict__ w2, const float* __restrict__ w3,
                       const float* __restrict__ wg, const float* __restrict__ wc1,
                       const float* __restrict__ att_src, const float* __restrict__ att_dst) {
    if (blockIdx.x == 160) {
        int tid = threadIdx.x;
        int k = tid >> 2, h = tid & 3;
        float ss = 0.f, sd = 0.f;
#pragma unroll
        for (int c = 0; c < 64; c++) {
            float w = wg[k * 256 + h * 64 + c];
            ss += w * att_src[h * 64 + c];
            sd += w * att_dst[h * 64 + c];
        }
        d_wz[k * 8 + h] = ss;
        d_wz[k * 8 + 4 + h] = sd;
        return;
    }
    int i = blockIdx.x * blockDim.x + threadIdx.x;
    if (i < 4096) d_w216[i] = __float2half_rn(w2[i]);
    else if (i < 8192) d_w316[i - 4096] = __float2half_rn(w3[i - 4096]);
    else if (i < 24576) d_wg16[i - 8192] = __float2half_rn(wg[i - 8192]);
    else if (i < 40960) d_wc116[i - 24576] = __float2half_rn(wc1[i - 24576]);
}

// ---------------- layer-1 GEMM (fp32 A, K=8) -> dinv-scaled fp16 out ----------
__global__ void k_gemm1(const float* __restrict__ A, const float* __restrict__ B,
                        __half* __restrict__ C, int n) {
    __shared__ float AsT[8][72];
    __shared__ ull   Bs2[8][32];
    int row0 = blockIdx.x * 64;
    int tid = threadIdx.x;
    int tx = tid & 15, ty = tid >> 4;
    ull acc[4][2] = {{0ull,0ull},{0ull,0ull},{0ull,0ull},{0ull,0ull}};
    for (int i = tid; i < 64 * 8; i += 256) {
        int r = i >> 3, k = i & 7;
        AsT[k][r] = (row0 + r < n) ? A[(size_t)(row0 + r) * 8 + k] : 0.f;
    }
    for (int i = tid; i < 8 * 32; i += 256) {
        int kk = i >> 5, c2 = i & 31;
        float2 bv = *reinterpret_cast<const float2*>(&B[(size_t)kk * 64 + 2 * c2]);
        Bs2[kk][c2] = pk2(bv.x, bv.y);
    }
    __syncthreads();
#pragma unroll
    for (int kk = 0; kk < 8; kk++) {
        float4 a4 = *reinterpret_cast<const float4*>(&AsT[kk][ty * 4]);
        ulonglong2 bp = *reinterpret_cast<const ulonglong2*>(&Bs2[kk][tx * 2]);
        ull b01 = bp.x, b23 = bp.y;
        ull a0 = pk2(a4.x, a4.x), a1 = pk2(a4.y, a4.y);
        ull a2 = pk2(a4.z, a4.z), a3 = pk2(a4.w, a4.w);
        ffma2(acc[0][0], a0, b01); ffma2(acc[0][1], a0, b23);
        ffma2(acc[1][0], a1, b01); ffma2(acc[1][1], a1, b23);
        ffma2(acc[2][0], a2, b01); ffma2(acc[2][1], a2, b23);
        ffma2(acc[3][0], a3, b01); ffma2(acc[3][1], a3, b23);
    }
#pragma unroll
    for (int i = 0; i < 4; i++) {
        int r = row0 + ty * 4 + i;
        if (r < n) {
            float dv = d_dinv[r];
            float2 c01 = up2(acc[i][0]), c23 = up2(acc[i][1]);
            __half2 h01 = __floats2half2_rn(dv * c01.x, dv * c01.y);
            __half2 h23 = __floats2half2_rn(dv * c23.x, dv * c23.y);
            uint2 v;
            v.x = *reinterpret_cast<unsigned*>(&h01);
            v.y = *reinterpret_cast<unsigned*>(&h23);
            *reinterpret_cast<uint2*>(&C[(size_t)r * 64 + tx * 4]) = v;
        }
    }
}

// ---------------- fp16 tensor-core GEMM (m16n8k16), tile 128x64 ---------------
__global__ void k_gemm_h(const __half* __restrict__ A, const __half* __restrict__ B16,
                         void* __restrict__ Cv, int n, int K, int ncols, int mode,
                         const float* __restrict__ bc1, const float* __restrict__ wc2,
                         const float* __restrict__ bc2, float* __restrict__ outp) {
    __shared__ __align__(16) unsigned char smbuf[34944];
    __half (*As)[72] = (__half(*)[72])smbuf;
    __half (*Bt)[72] = (__half(*)[72])(smbuf + 18432);
    float (*Z)[68]  = (float(*)[68])smbuf;

    int row0 = blockIdx.x * 128;
    int col0 = blockIdx.y * 64;
    int tid = threadIdx.x;
    int w = tid >> 5, lane = tid & 31;
    int qr = lane >> 2, q = lane & 3;

    float acc[8][4];
#pragma unroll
    for (int i = 0; i < 8; i++)
#pragma unroll
        for (int j = 0; j < 4; j++) acc[i][j] = 0.f;

    for (int k0 = 0; k0 < K; k0 += 64) {
        for (int i = tid * 8; i < 128 * 64; i += 256 * 8) {
            int r = i >> 6, k = i & 63;
            uint4 v = make_uint4(0u, 0u, 0u, 0u);
            if (row0 + r < n)
                v = *reinterpret_cast<const uint4*>(&A[(size_t)(row0 + r) * K + k0 + k]);
            *reinterpret_cast<uint4*>(&As[r][k]) = v;
        }
        for (int i = tid; i < 64 * 64; i += 256) {
            int c = i & 63, k = i >> 6;
            Bt[c][k] = B16[(size_t)(k0 + k) * ncols + col0 + c];
        }
        __syncthreads();
#pragma unroll
        for (int ks = 0; ks < 4; ks++) {
            int kb = ks * 16 + 2 * q;
            unsigned a0 = *reinterpret_cast<const unsigned*>(&As[w * 16 + qr][kb]);
            unsigned a1 = *reinterpret_cast<const unsigned*>(&As[w * 16 + qr + 8][kb]);
            unsigned a2 = *reinterpret_cast<const unsigned*>(&As[w * 16 + qr][kb + 8]);
            unsigned a3 = *reinterpret_cast<const unsigned*>(&As[w * 16 + qr + 8][kb + 8]);
#pragma unroll
            for (int nt = 0; nt < 8; nt++) {
                unsigned b0 = *reinterpret_cast<const unsigned*>(&Bt[nt * 8 + qr][kb]);
                unsigned b1 = *reinterpret_cast<const unsigned*>(&Bt[nt * 8 + qr][kb + 8]);
                mma16816(acc[nt], a0, a1, a2, a3, b0, b1);
            }
        }
        __syncthreads();
    }

    int r1 = row0 + w * 16 + qr;
    int r2 = r1 + 8;
    if (mode == 2 || mode == 3) {
        float dv1 = 1.f, dv2 = 1.f;
        if (mode == 3) {
            if (r1 < n) dv1 = d_dinv[r1];
            if (r2 < n) dv2 = d_dinv[r2];
        }
        __half* C = (__half*)Cv;
#pragma unroll
        for (int nt = 0; nt < 8; nt++) {
            int cb = col0 + nt * 8 + 2 * q;
            if (r1 < n) *reinterpret_cast<__half2*>(&C[(size_t)r1 * ncols + cb]) =
                __floats2half2_rn(dv1 * acc[nt][0], dv1 * acc[nt][1]);
            if (r2 < n) *reinterpret_cast<__half2*>(&C[(size_t)r2 * ncols + cb]) =
                __floats2half2_rn(dv2 * acc[nt][2], dv2 * acc[nt][3]);
        }
    } else {
#pragma unroll
        for (int nt = 0; nt < 8; nt++) {
            int cb = nt * 8 + 2 * q;
            Z[w * 16 + qr][cb]     = fmaxf(acc[nt][0] + bc1[cb], 0.f);
            Z[w * 16 + qr][cb + 1] = fmaxf(acc[nt][1] + bc1[cb + 1], 0.f);
            Z[w * 16 + qr + 8][cb]     = fmaxf(acc[nt][2] + bc1[cb], 0.f);
            Z[w * 16 + qr + 8][cb + 1] = fmaxf(acc[nt][3] + bc1[cb + 1], 0.f);
        }
        __syncthreads();
        if (tid < 128) {
            int node = row0 + tid;
            if (node < n) {
                float l0 = bc2[0], l1 = bc2[1], l2 = bc2[2];
#pragma unroll
                for (int k = 0; k < 64; k++) {
                    float zv = Z[tid][k];
                    l0 += zv * wc2[k * 3 + 0];
                    l1 += zv * wc2[k * 3 + 1];
                    l2 += zv * wc2[k * 3 + 2];
                }
                float mx = fmaxf(l0, fmaxf(l1, l2));
                float s = __expf(l0 - mx) + __expf(l1 - mx) + __expf(l2 - mx);
                float ls = mx + logf(s);
                outp[(size_t)node * 3 + 0] = l0 - ls;
                outp[(size_t)node * 3 + 1] = l1 - ls;
                outp[(size_t)node * 3 + 2] = l2 - ls;
            }
        }
    }
}

// ---------------- GCN aggregation (warp per node, staged idx, unroll 4) -------
__global__ void k_gcn_agg(const __half* __restrict__ t, const __half* hin,
                          const float* __restrict__ bias, __half* hout,
                          int n, int doAtt) {
    __shared__ int   g_s[8][64];
    __shared__ float Wz[64][8];
    int tid = threadIdx.x;
    if (doAtt) {
        for (int i = tid; i < 512; i += 256) Wz[i >> 3][i & 7] = d_wz[i];
        __syncthreads();
    }
    int ws = tid >> 5;
    int w = (blockIdx.x * blockDim.x + tid) >> 5;
    int lane = tid & 31;
    if (w >= n) return;
    int i0 = d_rowptr[w], i1 = d_rowptr[w + 1];
    float2 tv = __half22float2(reinterpret_cast<const __half2*>(t + (size_t)w * 64)[lane]);
    float a0 = tv.x, a1 = tv.y;

    for (int base = i0; base < i1; base += 64) {
        int cnt = min(64, i1 - base);
        for (int j = lane; j < cnt; j += 32) g_s[ws][j] = d_csr[base + j];
        __syncwarp();
        int j = 0;
        for (; j + 3 < cnt; j += 4) {
            int s0 = g_s[ws][j], s1 = g_s[ws][j + 1];
            int s2 = g_s[ws][j + 2], s3 = g_s[ws][j + 3];
            float2 x0 = __half22float2(reinterpret_cast<const __half2*>(t + (size_t)s0 * 64)[lane]);
            float2 x1 = __half22float2(reinterpret_cast<const __half2*>(t + (size_t)s1 * 64)[lane]);
            float2 x2 = __half22float2(reinterpret_cast<const __half2*>(t + (size_t)s2 * 64)[lane]);
            float2 x3 = __half22float2(reinterpret_cast<const __half2*>(t + (size_t)s3 * 64)[lane]);
            a0 += x0.x + x1.x + x2.x + x3.x;
            a1 += x0.y + x1.y + x2.y + x3.y;
        }
        for (; j < cnt; ++j) {
            int s = g_s[ws][j];
            float2 xs = __half22float2(reinterpret_cast<const __half2*>(t + (size_t)s * 64)[lane]);
            a0 += xs.x; a1 += xs.y;
        }
        __syncwarp();
    }
    float dv = d_dinv[w];
    float2 bv = *reinterpret_cast<const float2*>(bias + 2 * lane);
    a0 = fmaxf(dv * a0 + bv.x, 0.f);
    a1 = fmaxf(dv * a1 + bv.y, 0.f);
    if (hin) {
        float2 hv = __half22float2(reinterpret_cast<const __half2*>(hin + (size_t)w * 64)[lane]);
        a0 += hv.x; a1 += hv.y;
    }
    reinterpret_cast<__half2*>(hout + (size_t)w * 64)[lane] = __floats2half2_rn(a0, a1);

    if (doAtt) {
        float p0 = a0 * Wz[2 * lane][0] + a1 * Wz[2 * lane + 1][0];
        float p1 = a0 * Wz[2 * lane][1] + a1 * Wz[2 * lane + 1][1];
        float p2 = a0 * Wz[2 * lane][2] + a1 * Wz[2 * lane + 1][2];
        float p3 = a0 * Wz[2 * lane][3] + a1 * Wz[2 * lane + 1][3];
        float p4 = a0 * Wz[2 * lane][4] + a1 * Wz[2 * lane + 1][4];
        float p5 = a0 * Wz[2 * lane][5] + a1 * Wz[2 * lane + 1][5];
        float p6 = a0 * Wz[2 * lane][6] + a1 * Wz[2 * lane + 1][6];
        float p7 = a0 * Wz[2 * lane][7] + a1 * Wz[2 * lane + 1][7];
#pragma unroll
        for (int off = 16; off > 0; off >>= 1) {
            p0 += __shfl_xor_sync(0xffffffffu, p0, off);
            p1 += __shfl_xor_sync(0xffffffffu, p1, off);
            p2 += __shfl_xor_sync(0xffffffffu, p2, off);
            p3 += __shfl_xor_sync(0xffffffffu, p3, off);
            p4 += __shfl_xor_sync(0xffffffffu, p4, off);
            p5 += __shfl_xor_sync(0xffffffffu, p5, off);
            p6 += __shfl_xor_sync(0xffffffffu, p6, off);
            p7 += __shfl_xor_sync(0xffffffffu, p7, off);
        }
        if (lane == 0) {
            *reinterpret_cast<float4*>(d_att + (size_t)w * 8)     = make_float4(p0, p1, p2, p3);
            *reinterpret_cast<float4*>(d_att + (size_t)w * 8 + 4) = make_float4(p4, p5, p6, p7);
        }
    }
}

// ---------------- GAT aggregation (warp per node, LDG.128 per edge) -----------
#define ONLINE(mh, dh, ev) { float nm = fmaxf(mh, ev); dh = dh * __expf(mh - nm) + __expf(ev - nm); mh = nm; }
#define LRELU(x) ((x) > 0.f ? (x) : 0.2f * (x))

__global__ void k_gat(const float* __restrict__ bg, __half* __restrict__ hatt, int n) {
    __shared__ int   s_csr[8][64];
    __shared__ float s_alf[8][256];   // per edge j: alphas for heads 0..3 at j*4+h
    int ws = threadIdx.x >> 5;
    int v = (blockIdx.x * blockDim.x + threadIdx.x) >> 5;
    int lane = threadIdx.x & 31;
    if (v >= n) return;
    int hd = lane >> 3;               // this lane's head (cols 8*lane..8*lane+7)
    const float4* av4 = reinterpret_cast<const float4*>(d_att + (size_t)v * 8);
    float4 asv = av4[0], adv = av4[1];
    float ad0 = adv.x, ad1 = adv.y, ad2 = adv.z, ad3 = adv.w;
    int i0 = d_rowptr[v], i1 = d_rowptr[v + 1];

    // pass 1: strided online max/sum (4 heads) + cache first-64 logits
    float m0 = -1e30f, m1 = -1e30f, m2 = -1e30f, m3 = -1e30f;
    float s0 = 0.f, s1 = 0.f, s2 = 0.f, s3 = 0.f;
    for (int idx = i0 + lane; idx < i1; idx += 32) {
        int sn = d_csr[idx];
        float4 a = *reinterpret_cast<const float4*>(d_att + (size_t)sn * 8);
        float e0 = LRELU(a.x + ad0), e1 = LRELU(a.y + ad1);
        float e2 = LRELU(a.z + ad2), e3 = LRELU(a.w + ad3);
        int j = idx - i0;
        if (j < 64) {
            s_csr[ws][j] = sn;
            *reinterpret_cast<float4*>(&s_alf[ws][j * 4]) = make_float4(e0, e1, e2, e3);
        }
        ONLINE(m0, s0, e0); ONLINE(m1, s1, e1);
        ONLINE(m2, s2, e2); ONLINE(m3, s3, e3);
    }
#pragma unroll
    for (int off = 16; off > 0; off >>= 1) {
#define RED(mh, dh) { float om = __shfl_xor_sync(0xffffffffu, mh, off); \
                      float od = __shfl_xor_sync(0xffffffffu, dh, off); \
                      float nm = fmaxf(mh, om); \
                      dh = dh * __expf(mh - nm) + od * __expf(om - nm); mh = nm; }
        RED(m0, s0) RED(m1, s1) RED(m2, s2) RED(m3, s3)
#undef RED
    }
    float e0 = LRELU(asv.x + ad0); ONLINE(m0, s0, e0);
    float e1 = LRELU(asv.y + ad1); ONLINE(m1, s1, e1);
    float e2 = LRELU(asv.z + ad2); ONLINE(m2, s2, e2);
    float e3 = LRELU(asv.w + ad3); ONLINE(m3, s3, e3);
    float inv0 = 1.f / (s0 + 1e-16f), inv1 = 1.f / (s1 + 1e-16f);
    float inv2 = 1.f / (s2 + 1e-16f), inv3 = 1.f / (s3 + 1e-16f);

    // self contribution: one uint4 (8 halves) per lane = cols 8l..8l+7
    ull acc0, acc1, acc2, acc3;
    {
        float af0 = __expf(e0 - m0) * inv0, af1 = __expf(e1 - m1) * inv1;
        float af2 = __expf(e2 - m2) * inv2, af3 = __expf(e3 - m3) * inv3;
        float afl = hd == 0 ? af0 : hd == 1 ? af1 : hd == 2 ? af2 : af3;
        uint4 raw = reinterpret_cast<const uint4*>(d_hgh + (size_t)v * 256)[lane];
        float2 f0 = __half22float2(*reinterpret_cast<__half2*>(&raw.x));
        float2 f1 = __half22float2(*reinterpret_cast<__half2*>(&raw.y));
        float2 f2 = __half22float2(*reinterpret_cast<__half2*>(&raw.z));
        float2 f3 = __half22float2(*reinterpret_cast<__half2*>(&raw.w));
        acc0 = pk2(afl * f0.x, afl * f0.y);
        acc1 = pk2(afl * f1.x, afl * f1.y);
        acc2 = pk2(afl * f2.x, afl * f2.y);
        acc3 = pk2(afl * f3.x, afl * f3.y);
    }

    // pass 2 chunks: strided alpha staging, serial aggregation (1 LDG.128/edge)
    for (int base = i0; base < i1; base += 64) {
        int cnt = min(64, i1 - base);
        if (base == i0) {
            for (int j = lane; j < cnt; j += 32) {
                float4 ev = *reinterpret_cast<const float4*>(&s_alf[ws][j * 4]);
                *reinterpret_cast<float4*>(&s_alf[ws][j * 4]) =
                    make_float4(__expf(ev.x - m0) * inv0, __expf(ev.y - m1) * inv1,
                                __expf(ev.z - m2) * inv2, __expf(ev.w - m3) * inv3);
            }
        } else {
            for (int j = lane; j < cnt; j += 32) {
                int sn = d_csr[base + j];
                s_csr[ws][j] = sn;
                float4 a = *reinterpret_cast<const float4*>(d_att + (size_t)sn * 8);
                *reinterpret_cast<float4*>(&s_alf[ws][j * 4]) = make_float4(
                    __expf(LRELU(a.x + ad0) - m0) * inv0,
                    __expf(LRELU(a.y + ad1) - m1) * inv1,
                    __expf(LRELU(a.z + ad2) - m2) * inv2,
                    __expf(LRELU(a.w + ad3) - m3) * inv3);
            }
        }
        __syncwarp();
        int j = 0;
        for (; j + 1 < cnt; j += 2) {
            int sn0 = s_csr[ws][j], sn1 = s_csr[ws][j + 1];
            float alA = s_alf[ws][j * 4 + hd];
            float alB = s_alf[ws][j * 4 + 4 + hd];
            uint4 ra = reinterpret_cast<const uint4*>(d_hgh + (size_t)sn0 * 256)[lane];
            uint4 rb = reinterpret_cast<const uint4*>(d_hgh + (size_t)sn1 * 256)[lane];
            ull pa = pk2(alA, alA), pb = pk2(alB, alB);
            float2 f0 = __half22float2(*reinterpret_cast<__half2*>(&ra.x));
            float2 f1 = __half22float2(*reinterpret_cast<__half2*>(&ra.y));
            float2 f2 = __half22float2(*reinterpret_cast<__half2*>(&ra.z));
            float2 f3 = __half22float2(*reinterpret_cast<__half2*>(&ra.w));
            ffma2(acc0, pa, pk2(f0.x, f0.y));
            ffma2(acc1, pa, pk2(f1.x, f1.y));
            ffma2(acc2, pa, pk2(f2.x, f2.y));
            ffma2(acc3, pa, pk2(f3.x, f3.y));
            float2 g0 = __half22float2(*reinterpret_cast<__half2*>(&rb.x));
            float2 g1 = __half22float2(*reinterpret_cast<__half2*>(&rb.y));
            float2 g2 = __half22float2(*reinterpret_cast<__half2*>(&rb.z));
            float2 g3 = __half22float2(*reinterpret_cast<__half2*>(&rb.w));
            ffma2(acc0, pb, pk2(g0.x, g0.y));
            ffma2(acc1, pb, pk2(g1.x, g1.y));
            ffma2(acc2, pb, pk2(g2.x, g2.y));
            ffma2(acc3, pb, pk2(g3.x, g3.y));
        }
        if (j < cnt) {
            int sn = s_csr[ws][j];
            float alA = s_alf[ws][j * 4 + hd];
            uint4 ra = reinterpret_cast<const uint4*>(d_hgh + (size_t)sn * 256)[lane];
            ull pa = pk2(alA, alA);
            float2 f0 = __half22float2(*reinterpret_cast<__half2*>(&ra.x));
            float2 f1 = __half22float2(*reinterpret_cast<__half2*>(&ra.y));
            float2 f2 = __half22float2(*reinterpret_cast<__half2*>(&ra.z));
            float2 f3 = __half22float2(*reinterpret_cast<__half2*>(&ra.w));
            ffma2(acc0, pa, pk2(f0.x, f0.y));
            ffma2(acc1, pa, pk2(f1.x, f1.y));
            ffma2(acc2, pa, pk2(f2.x, f2.y));
            ffma2(acc3, pa, pk2(f3.x, f3.y));
        }
        __syncwarp();
    }
    // output: cols 8*lane .. 8*lane+7 (one uint4 store)
    {
        float2 a0 = up2(acc0), a1 = up2(acc1), a2 = up2(acc2), a3 = up2(acc3);
        float4 b0 = *reinterpret_cast<const float4*>(&bg[8 * lane]);
        float4 b1 = *reinterpret_cast<const float4*>(&bg[8 * lane + 4]);
        __half2 h0 = __floats2half2_rn(a0.x + b0.x, a0.y + b0.y);
        __half2 h1 = __floats2half2_rn(a1.x + b0.z, a1.y + b0.w);
        __half2 h2 = __floats2half2_rn(a2.x + b1.x, a2.y + b1.y);
        __half2 h3 = __floats2half2_rn(a3.x + b1.z, a3.y + b1.w);
        uint4 o;
        o.x = *reinterpret_cast<unsigned*>(&h0);
        o.y = *reinterpret_cast<unsigned*>(&h1);
        o.z = *reinterpret_cast<unsigned*>(&h2);
        o.w = *reinterpret_cast<unsigned*>(&h3);
        reinterpret_cast<uint4*>(hatt + (size_t)v * 256)[lane] = o;
    }
}

// ---------------- launch ----------------
extern "C" void kernel_launch(void* const* d_in, const int* in_sizes, int n_in,
                              void* d_out, int out_size) {
    const float* x        = (const float*)d_in[0];
    const int*   ei       = (const int*)d_in[1];
    const float* w1       = (const float*)d_in[2];
    const float* b1       = (const float*)d_in[3];
    const float* w2       = (const float*)d_in[4];
    const float* b2       = (const float*)d_in[5];
    const float* w3       = (const float*)d_in[6];
    const float* b3       = (const float*)d_in[7];
    const float* wg       = (const float*)d_in[8];
    const float* bg       = (const float*)d_in[9];
    const float* att_src  = (const float*)d_in[10];
    const float* att_dst  = (const float*)d_in[11];
    const float* wc1      = (const float*)d_in[12];
    const float* bc1      = (const float*)d_in[13];
    const float* wc2      = (const float*)d_in[14];
    const float* bc2      = (const float*)d_in[15];
    float* out = (float*)d_out;

    int n = in_sizes[0] / 8;
    int e = in_sizes[1] / 2;
    const int* src = ei;
    const int* dst = ei + e;

    __half *t16, *h16, *hgh, *hatt, *w216, *w316, *wg16, *wc116;
    int* cnt;
    cudaGetSymbolAddress((void**)&t16,   d_t16);
    cudaGetSymbolAddress((void**)&h16,   d_h16);
    cudaGetSymbolAddress((void**)&hgh,   d_hgh);
    cudaGetSymbolAddress((void**)&hatt,  d_hatt);
    cudaGetSymbolAddress((void**)&w216,  d_w216);
    cudaGetSymbolAddress((void**)&w316,  d_w316);
    cudaGetSymbolAddress((void**)&wg16,  d_wg16);
    cudaGetSymbolAddress((void**)&wc116, d_wc116);
    cudaGetSymbolAddress((void**)&cnt,   d_cnt);

    int nb1024 = (n + 1023) / 1024;
    int gN = (n + 255) / 256;
    int gE = (e + 255) / 256;
    int gW = (n + 7) / 8;
    int gM64 = (n + 63) / 64;
    int gM = (n + 127) / 128;

    // CSR build + weight prep
    cudaMemsetAsync(cnt, 0, (size_t)n * sizeof(int));
    k_count<<<gE, 256>>>(dst, e);
    k_scan_blocks<<<nb1024, 1024>>>(n);
    k_scan_off<<<1, 512>>>(nb1024);
    k_fixup<<<gN, 256>>>(n, e);
    k_fill<<<gE, 256>>>(src, dst, e);
    k_prep<<<161, 256>>>(w2, w3, wg, wc1, att_src, att_dst);

    // GCN layer 1
    k_gemm1<<<gM64, 256>>>(x, w1, t16, n);
    k_gcn_agg<<<gW, 256>>>(t16, nullptr, b1, h16, n, 0);
    // GCN layer 2 (residual, in-place h16)
    k_gemm_h<<<dim3(gM, 1), 256>>>(h16, w216, t16, n, 64, 64, 3, nullptr, nullptr, nullptr, nullptr);
    k_gcn_agg<<<gW, 256>>>(t16, h16, b2, h16, n, 0);
    // GCN layer 3 (residual + fused attention logits)
    k_gemm_h<<<dim3(gM, 1), 256>>>(h16, w316, t16, n, 64, 64, 3, nullptr, nullptr, nullptr, nullptr);
    k_gcn_agg<<<gW, 256>>>(t16, h16, b3, h16, n, 1);

    // GAT
    k_gemm_h<<<dim3(gM, 4), 256>>>(h16, wg16, hgh, n, 64, 256, 2, nullptr, nullptr, nullptr, nullptr);
    k_gat<<<gW, 256>>>(bg, hatt, n);

    // classifier MLP + log_softmax
    k_gemm_h<<<dim3(gM, 1), 256>>>(hatt, wc116, nullptr, n, 256, 64, 1, bc1, wc2, bc2, out);
}